// round 12
// baseline (speedup 1.0000x reference)
#include <cuda_runtime.h>
#include <cstdint>
#include <cstddef>

#define BB 4
#define NN 16384
#define NPT 1024
#define NS 32
#define CF 64
#define CIN 67
#define CL 4  // CTAs per cluster (one cluster per batch)

// scratch: neighbor indices (B, NPOINT, NSAMPLE)
__device__ int g_nidx[BB * NPT * NS];

// ---- packed f32x2 helpers (per-lane IEEE rn, identical to scalar __fadd_rn/__fmul_rn)
typedef unsigned long long u64;
__device__ __forceinline__ u64 f2_add(u64 a, u64 b) {
    u64 r;
    asm("add.rn.f32x2 %0, %1, %2;" : "=l"(r) : "l"(a), "l"(b));
    return r;
}
__device__ __forceinline__ u64 f2_mul(u64 a, u64 b) {
    u64 r;
    asm("mul.rn.f32x2 %0, %1, %2;" : "=l"(r) : "l"(a), "l"(b));
    return r;
}
__device__ __forceinline__ u64 f2_pack(float lo, float hi) {
    u64 r;
    asm("mov.b64 %0, {%1, %2};" : "=l"(r) : "f"(lo), "f"(hi));
    return r;
}
__device__ __forceinline__ float2 f2_unpack(u64 v) {
    float2 r;
    asm("mov.b64 {%0, %1}, %2;" : "=f"(r.x), "=f"(r.y) : "l"(v));
    return r;
}
__device__ __forceinline__ u64 umax64(u64 a, u64 b) { return a > b ? a : b; }
__device__ __forceinline__ uint32_t redux_max(uint32_t v) {
    uint32_t r;
    asm("redux.sync.max.u32 %0, %1, 0xffffffff;" : "=r"(r) : "r"(v));
    return r;
}
__device__ __forceinline__ uint32_t smem_u32(const void* p) {
    return (uint32_t)__cvta_generic_to_shared(p);
}
__device__ __forceinline__ void st_cluster_u64(uint32_t laddr, uint32_t rank, u64 v) {
    uint32_t r;
    asm volatile("mapa.shared::cluster.u32 %0, %1, %2;" : "=r"(r) : "r"(laddr), "r"(rank));
    asm volatile("st.relaxed.cluster.shared::cluster.u64 [%0], %1;" ::"r"(r), "l"(v)
                 : "memory");
}
__device__ __forceinline__ u64 ld_mbox(uint32_t laddr) {
    u64 v;
    asm volatile("ld.relaxed.cluster.shared::cta.u64 %0, [%1];" : "=l"(v) : "r"(laddr)
                 : "memory");
    return v;
}
__device__ __forceinline__ void cluster_sync_all() {
    asm volatile("barrier.cluster.arrive.aligned;" ::: "memory");
    asm volatile("barrier.cluster.wait.aligned;" ::: "memory");
}

// mailbox word: (p+1)(11b) << 53 | dist_bits(32b) << 21 | negidx(14b)
// Equal tags -> u64 max == (dist, -idx) lexicographic max == jnp.argmax semantics.
// Tag bits also guarantee any real message > 0, so zero-filled lanes never win.

// ---------------------------------------------------------------------------
// FPS: 4-CTA cluster per batch. Full packed xyz copy per CTA (slot s packs
// points (s, s+8192)); each CTA updates dists for its own 4096 points, whose
// coords are hoisted into registers. Only warp 0's lanes 0-3 ever touch the
// cluster path (publish + poll). Warps 1-31 wait at a plain __syncthreads
// (scheduler sleep, zero fabric traffic) and pick up the winner from smem.
// This removes the 4096-thread cluster-load storm that serialized against
// the publisher's DSMEM stores in earlier rounds.
// Deadlock-free: each rank publishes all 4 copies BEFORE polling; WAR-safe:
// parity slot for p is only rewritten (at p+2) after every rank passed its
// bar#2 of p+1, which transitively requires universal consumption of p.
// ---------------------------------------------------------------------------
__global__ __launch_bounds__(1024, 1) __cluster_dims__(CL, 1, 1)
void fps_kernel(const float* __restrict__ xyz, float* __restrict__ newxyz) {
    extern __shared__ unsigned char smraw[];
    ulonglong2* A = (ulonglong2*)smraw;            // 8192 x 16B = 128 KB
    u64* Z = (u64*)(smraw + 8192 * 16);            // 8192 x 8B  =  64 KB
    __shared__ u64 s_part[32];
    __shared__ u64 mbox[2][CL];                    // [parity][rank]
    __shared__ int s_f;

    const int b = blockIdx.x / CL;
    const int rank = blockIdx.x % CL;
    const int tid = threadIdx.x;
    const float* base = xyz + (size_t)b * NN * 3;

    // full packed copy (every CTA)
    for (int s = tid; s < 8192; s += 1024) {
        const int ia = s, ib = s + 8192;
        ulonglong2 av;
        av.x = f2_pack(base[3 * ia + 0], base[3 * ib + 0]);
        av.y = f2_pack(base[3 * ia + 1], base[3 * ib + 1]);
        A[s] = av;
        Z[s] = f2_pack(base[3 * ia + 2], base[3 * ib + 2]);
    }
    if (tid < 2 * CL) ((u64*)mbox)[tid] = 0;  // tags start at 1; 0 never matches

    const int s0 = rank * 2048 + tid;  // this thread's two packed slots
    const int s1 = s0 + 1024;
    const uint32_t ni0a = (uint32_t)(16383 - s0);
    const uint32_t ni0b = (uint32_t)(16383 - (s0 + 8192));
    const uint32_t ni1a = (uint32_t)(16383 - s1);
    const uint32_t ni1b = (uint32_t)(16383 - (s1 + 8192));

    float2 d20 = make_float2(1e10f, 1e10f);
    float2 d21 = make_float2(1e10f, 1e10f);

    __syncthreads();
    cluster_sync_all();  // tiles + mailboxes initialized cluster-wide from here

    // hoist loop-invariant point coords into registers
    const ulonglong2 av0 = A[s0];
    const u64 zv0 = Z[s0];
    const ulonglong2 av1 = A[s1];
    const u64 zv1 = Z[s1];

    int f = 0;
    float* outp = newxyz + (size_t)b * NPT * 3;
    const int lane = tid & 31, wid = tid >> 5;
    const uint32_t mb0 = smem_u32(&mbox[0][0]);

    for (int p = 0; p < NPT; ++p) {
        // centroid fetch (local, full copy)
        const int fslot = f & 8191;
        const int fhalf = f >> 13;
        const ulonglong2 fa = A[fslot];
        const float2 fx = f2_unpack(fa.x);
        const float2 fy = f2_unpack(fa.y);
        const float2 fz = f2_unpack(Z[fslot]);
        const float cx = fhalf ? fx.y : fx.x;
        const float cy = fhalf ? fy.y : fy.x;
        const float cz = fhalf ? fz.y : fz.x;
        if (rank == 0 && tid == 0) {
            outp[3 * p + 0] = cx;
            outp[3 * p + 1] = cy;
            outp[3 * p + 2] = cz;
        }
        const u64 ncx = f2_pack(-cx, -cx);
        const u64 ncy = f2_pack(-cy, -cy);
        const u64 ncz = f2_pack(-cz, -cz);

        u64 loc;
        {
            const u64 dx = f2_add(av0.x, ncx);
            const u64 dy = f2_add(av0.y, ncy);
            const u64 dz = f2_add(zv0, ncz);
            const float2 d =
                f2_unpack(f2_add(f2_add(f2_mul(dx, dx), f2_mul(dy, dy)), f2_mul(dz, dz)));
            d20.x = fminf(d20.x, d.x);
            d20.y = fminf(d20.y, d.y);
            const u64 k0 = ((u64)__float_as_uint(d20.x) << 21) | ni0a;
            const u64 k1 = ((u64)__float_as_uint(d20.y) << 21) | ni0b;
            loc = umax64(k0, k1);
        }
        {
            const u64 dx = f2_add(av1.x, ncx);
            const u64 dy = f2_add(av1.y, ncy);
            const u64 dz = f2_add(zv1, ncz);
            const float2 d =
                f2_unpack(f2_add(f2_add(f2_mul(dx, dx), f2_mul(dy, dy)), f2_mul(dz, dz)));
            d21.x = fminf(d21.x, d.x);
            d21.y = fminf(d21.y, d.y);
            const u64 k0 = ((u64)__float_as_uint(d21.x) << 21) | ni1a;
            const u64 k1 = ((u64)__float_as_uint(d21.y) << 21) | ni1b;
            loc = umax64(loc, umax64(k0, k1));
        }

        // warp argmax via two redux ops
        {
            const uint32_t dbits = (uint32_t)(loc >> 21);
            const uint32_t wmax = redux_max(dbits);
            const uint32_t cand = (dbits == wmax) ? (uint32_t)(loc & 0x3FFFu) : 0u;
            const uint32_t nmax = redux_max(cand);
            if (lane == 0) s_part[wid] = ((u64)wmax << 21) | nmax;
        }
        __syncthreads();  // bar #1: partials visible to warp 0

        const int par = p & 1;
        const u64 tag = (u64)(p + 1);
        if (wid == 0) {
            // stage 2: reduce the 32 CTA partials
            const u64 v = s_part[lane];
            const uint32_t dbits = (uint32_t)(v >> 21);
            const uint32_t wmax = redux_max(dbits);
            const uint32_t cand = (dbits == wmax) ? (uint32_t)(v & 0x3FFFu) : 0u;
            const uint32_t nmax = redux_max(cand);
            const u64 msg = (tag << 53) | ((u64)wmax << 21) | nmax;
            // lanes 0..3: publish to rank `lane`, then poll word `lane`
            u64 got = 0;
            if (lane < CL) {
                const uint32_t off = (uint32_t)(par * CL) * 8u;
                st_cluster_u64(mb0 + off + (uint32_t)rank * 8u, (uint32_t)lane, msg);
                const uint32_t a = mb0 + off + (uint32_t)lane * 8u;
                do {
                    got = ld_mbox(a);
                } while ((got >> 53) != tag);
            }
            // combine the 4 tagged words (zeros from lanes >= 4 never win)
            got = umax64(got, __shfl_xor_sync(0xffffffffu, got, 1));
            got = umax64(got, __shfl_xor_sync(0xffffffffu, got, 2));
            if (lane == 0) s_f = 16383 - (int)(got & 0x3FFFu);
        }
        __syncthreads();  // bar #2: winner published; warps 1-31 slept here
        f = s_f;
    }
    cluster_sync_all();  // no CTA exits while peers may still store into it
}

// ---------------------------------------------------------------------------
// Ball query: one warp per centroid, 256-thr blocks, no smem (high occupancy).
// Scan points in index order, append the first 32 within radius
// (strict d2 < 0.01f), pad with the first hit.
// ---------------------------------------------------------------------------
__global__ __launch_bounds__(256) void ball_kernel(const float* __restrict__ xyz,
                                                   const float* __restrict__ newxyz) {
    const int gw = (int)((blockIdx.x * blockDim.x + threadIdx.x) >> 5);
    const int lane = threadIdx.x & 31;
    if (gw >= BB * NPT) return;
    const int b = gw >> 10;

    const float* nx = newxyz + (size_t)gw * 3;
    const float cx = nx[0], cy = nx[1], cz = nx[2];
    const float* px = xyz + (size_t)b * NN * 3;
    int* out = g_nidx + (size_t)gw * NS;

    int count = 0;
    int first = 0;
    bool havefirst = false;

    for (int bs = 0; bs < NN; bs += 32) {
        const int i = bs + lane;
        const float dx = __fadd_rn(px[3 * i + 0], -cx);
        const float dy = __fadd_rn(px[3 * i + 1], -cy);
        const float dz = __fadd_rn(px[3 * i + 2], -cz);
        const float d2 =
            __fadd_rn(__fadd_rn(__fmul_rn(dx, dx), __fmul_rn(dy, dy)), __fmul_rn(dz, dz));
        const bool win = d2 < 0.01f;
        const unsigned m = __ballot_sync(0xffffffffu, win);
        if (m) {
            if (!havefirst) {
                first = bs + __ffs(m) - 1;
                havefirst = true;
            }
            const int slot = count + __popc(m & ((1u << lane) - 1u));
            if (win && slot < NS) out[slot] = i;
            count += __popc(m);
            if (count >= NS) break;
        }
    }
    if (lane >= count) out[lane] = first;  // pad (count<32 case); no-op if count>=32
}

// ---------------------------------------------------------------------------
// Gather + 3-layer MLP + max-pool (round-4 version: in-register h1/h2,
// 67.5 KB smem -> 3 CTAs/SM). One warp per centroid, lane = sample.
// Weights in smem (LDS.128 broadcast, 1 LDS : 4 FMA). 8-wide accumulator ILP.
// ---------------------------------------------------------------------------
__global__ __launch_bounds__(128) void mlp_kernel(
    const float* __restrict__ xyz, const float* __restrict__ feat,
    const float* __restrict__ w1, const float* __restrict__ b1,
    const float* __restrict__ w2, const float* __restrict__ b2,
    const float* __restrict__ w3, const float* __restrict__ b3,
    const float* __restrict__ newxyz, float* __restrict__ outf) {
    extern __shared__ float sm[];
    float* sw1 = sm;                 // 64 x 68 (padded)
    float* sw2 = sw1 + 64 * 68;      // 64 x 64
    float* sw3 = sw2 + 64 * 64;      // 128 x 64
    float* sb1 = sw3 + 128 * 64;     // 64
    float* sb2 = sb1 + 64;           // 64
    float* sb3 = sb2 + 64;           // 128

    const int tid = threadIdx.x;
    for (int i = tid; i < 64 * CIN; i += 128) sw1[(i / CIN) * 68 + (i % CIN)] = w1[i];
    for (int i = tid; i < 64 * 64; i += 128) sw2[i] = w2[i];
    for (int i = tid; i < 128 * 64; i += 128) sw3[i] = w3[i];
    if (tid < 64) {
        sb1[tid] = b1[tid];
        sb2[tid] = b2[tid];
    }
    if (tid < 128) sb3[tid] = b3[tid];
    __syncthreads();

    const int warp = tid >> 5, lane = tid & 31;
    const int pc = blockIdx.x * 4 + warp;  // global centroid id
    const int b = pc >> 10, p = pc & 1023;

    const int idx = g_nidx[pc * NS + lane];
    const float* P = xyz + ((size_t)b * NN + idx) * 3;
    const float* NXp = newxyz + (size_t)pc * 3;

    float in[CIN];
    in[0] = P[0] - NXp[0];
    in[1] = P[1] - NXp[1];
    in[2] = P[2] - NXp[2];
    const float4* F = (const float4*)(feat + ((size_t)b * NN + idx) * CF);
#pragma unroll
    for (int q = 0; q < 16; q++) {
        const float4 v = F[q];
        in[3 + 4 * q] = v.x;
        in[4 + 4 * q] = v.y;
        in[5 + 4 * q] = v.z;
        in[6 + 4 * q] = v.w;
    }

    float h1[64] __attribute__((aligned(16)));
#pragma unroll 1
    for (int o = 0; o < 64; o += 8) {
        float acc[8];
#pragma unroll
        for (int j = 0; j < 8; j++) acc[j] = sb1[o + j];
#pragma unroll
        for (int c = 0; c < 64; c += 4) {
#pragma unroll
            for (int j = 0; j < 8; j++) {
                const float4 w = *(const float4*)&sw1[(o + j) * 68 + c];
                acc[j] = fmaf(in[c + 0], w.x, acc[j]);
                acc[j] = fmaf(in[c + 1], w.y, acc[j]);
                acc[j] = fmaf(in[c + 2], w.z, acc[j]);
                acc[j] = fmaf(in[c + 3], w.w, acc[j]);
            }
        }
#pragma unroll
        for (int j = 0; j < 8; j++) {
            acc[j] = fmaf(in[64], sw1[(o + j) * 68 + 64], acc[j]);
            acc[j] = fmaf(in[65], sw1[(o + j) * 68 + 65], acc[j]);
            acc[j] = fmaf(in[66], sw1[(o + j) * 68 + 66], acc[j]);
            h1[o + j] = fmaxf(acc[j], 0.0f);
        }
    }

    float h2[64] __attribute__((aligned(16)));
#pragma unroll 1
    for (int o = 0; o < 64; o += 8) {
        float acc[8];
#pragma unroll
        for (int j = 0; j < 8; j++) acc[j] = sb2[o + j];
#pragma unroll
        for (int c = 0; c < 64; c += 4) {
            const float4 hv = *(const float4*)&h1[c];
#pragma unroll
            for (int j = 0; j < 8; j++) {
                const float4 w = *(const float4*)&sw2[(o + j) * 64 + c];
                acc[j] = fmaf(hv.x, w.x, acc[j]);
                acc[j] = fmaf(hv.y, w.y, acc[j]);
                acc[j] = fmaf(hv.z, w.z, acc[j]);
                acc[j] = fmaf(hv.w, w.w, acc[j]);
            }
        }
#pragma unroll
        for (int j = 0; j < 8; j++) h2[o + j] = fmaxf(acc[j], 0.0f);
    }

    const size_t obase = ((size_t)b * 128) * NPT + p;
#pragma unroll 1
    for (int o = 0; o < 128; o += 8) {
        float acc[8];
#pragma unroll
        for (int j = 0; j < 8; j++) acc[j] = sb3[o + j];
#pragma unroll
        for (int c = 0; c < 64; c += 4) {
            const float4 hv = *(const float4*)&h2[c];
#pragma unroll
            for (int j = 0; j < 8; j++) {
                const float4 w = *(const float4*)&sw3[(o + j) * 64 + c];
                acc[j] = fmaf(hv.x, w.x, acc[j]);
                acc[j] = fmaf(hv.y, w.y, acc[j]);
                acc[j] = fmaf(hv.z, w.z, acc[j]);
                acc[j] = fmaf(hv.w, w.w, acc[j]);
            }
        }
#pragma unroll
        for (int j = 0; j < 8; j++) {
            float v = fmaxf(acc[j], 0.0f);  // relu then max over samples
#pragma unroll
            for (int off = 16; off; off >>= 1)
                v = fmaxf(v, __shfl_xor_sync(0xffffffffu, v, off));
            if (lane == 0) outf[obase + (size_t)(o + j) * NPT] = v;
        }
    }
}

// ---------------------------------------------------------------------------
extern "C" void kernel_launch(void* const* d_in, const int* in_sizes, int n_in,
                              void* d_out, int out_size) {
    const float* xyz = (const float*)d_in[0];
    const float* feat = (const float*)d_in[1];
    const float* w1 = (const float*)d_in[2];
    const float* b1 = (const float*)d_in[3];
    const float* w2 = (const float*)d_in[4];
    const float* b2 = (const float*)d_in[5];
    const float* w3 = (const float*)d_in[6];
    const float* b3 = (const float*)d_in[7];

    float* out = (float*)d_out;
    float* newxyz = out;                  // (B, NPOINT, 3)
    float* outf = out + BB * NPT * 3;     // (B, 128, NPOINT)

    const int fps_smem = 8192 * 16 + 8192 * 8;  // 196608 B (full packed copy)
    const int mlp_smem = (64 * 68 + 64 * 64 + 128 * 64 + 64 + 64 + 128) * 4;  // 67584 B

    cudaFuncSetAttribute(fps_kernel, cudaFuncAttributeMaxDynamicSharedMemorySize, fps_smem);
    cudaFuncSetAttribute(mlp_kernel, cudaFuncAttributeMaxDynamicSharedMemorySize, mlp_smem);

    fps_kernel<<<BB * CL, 1024, fps_smem>>>(xyz, newxyz);
    ball_kernel<<<(BB * NPT * 32) / 256, 256>>>(xyz, newxyz);
    mlp_kernel<<<BB * NPT / 4, 128, mlp_smem>>>(xyz, feat, w1, b1, w2, b2, w3, b3, newxyz, outf);
}

// round 13
// speedup vs baseline: 1.4012x; 1.4012x over previous
#include <cuda_runtime.h>
#include <cstdint>
#include <cstddef>

#define BB 4
#define NN 16384
#define NPT 1024
#define NS 32
#define CF 64
#define CIN 67
#define CL 4                 // CTAs per FPS cluster (one cluster per batch)
#define NFPS (BB * CL)       // 16 FPS blocks
#define NWORK 136            // worker blocks (16+136 = 152 = GB300 SM count)
#define WWARPS 15            // worker warps per worker CTA (warp 0 = poller)
#define TOTWW (NWORK * WWARPS)  // 2040 centroid warps

// cross-kernel progress: centroids published per batch
__device__ int g_progress[BB];

// ---- packed f32x2 helpers (per-lane IEEE rn, identical to scalar __fadd_rn/__fmul_rn)
typedef unsigned long long u64;
__device__ __forceinline__ u64 f2_add(u64 a, u64 b) {
    u64 r;
    asm("add.rn.f32x2 %0, %1, %2;" : "=l"(r) : "l"(a), "l"(b));
    return r;
}
__device__ __forceinline__ u64 f2_mul(u64 a, u64 b) {
    u64 r;
    asm("mul.rn.f32x2 %0, %1, %2;" : "=l"(r) : "l"(a), "l"(b));
    return r;
}
__device__ __forceinline__ u64 f2_pack(float lo, float hi) {
    u64 r;
    asm("mov.b64 %0, {%1, %2};" : "=l"(r) : "f"(lo), "f"(hi));
    return r;
}
__device__ __forceinline__ float2 f2_unpack(u64 v) {
    float2 r;
    asm("mov.b64 {%0, %1}, %2;" : "=f"(r.x), "=f"(r.y) : "l"(v));
    return r;
}
__device__ __forceinline__ u64 umax64(u64 a, u64 b) { return a > b ? a : b; }
__device__ __forceinline__ uint32_t redux_max(uint32_t v) {
    uint32_t r;
    asm("redux.sync.max.u32 %0, %1, 0xffffffff;" : "=r"(r) : "r"(v));
    return r;
}
__device__ __forceinline__ uint32_t smem_u32(const void* p) {
    return (uint32_t)__cvta_generic_to_shared(p);
}
__device__ __forceinline__ void st_cluster_u64(uint32_t laddr, uint32_t rank, u64 v) {
    uint32_t r;
    asm volatile("mapa.shared::cluster.u32 %0, %1, %2;" : "=r"(r) : "r"(laddr), "r"(rank));
    asm volatile("st.relaxed.cluster.shared::cluster.u64 [%0], %1;" ::"r"(r), "l"(v)
                 : "memory");
}
__device__ __forceinline__ u64 ld_mbox(uint32_t laddr) {
    u64 v;
    asm volatile("ld.relaxed.cluster.shared::cta.u64 %0, [%1];" : "=l"(v) : "r"(laddr)
                 : "memory");
    return v;
}
__device__ __forceinline__ void st_release_gpu(int* p, int v) {
    asm volatile("st.release.gpu.u32 [%0], %1;" ::"l"(p), "r"(v) : "memory");
}
__device__ __forceinline__ int ld_acquire_gpu(const int* p) {
    int v;
    asm volatile("ld.acquire.gpu.u32 %0, [%1];" : "=r"(v) : "l"(p) : "memory");
    return v;
}
__device__ __forceinline__ void cluster_sync_all() {
    asm volatile("barrier.cluster.arrive.aligned;" ::: "memory");
    asm volatile("barrier.cluster.wait.aligned;" ::: "memory");
}

__global__ void reset_kernel() {
    if ((int)threadIdx.x < BB) g_progress[threadIdx.x] = 0;
}

// mailbox word: (p+1)(11b) << 53 | dist_bits(32b) << 21 | negidx(14b)
// Equal tags -> u64 max == (dist, -idx) lexicographic max == jnp.argmax semantics.

// ---------------------------------------------------------------------------
// Fused persistent kernel.
//  blocks 0..15   : FPS, round-4 structure (4-CTA cluster per batch, full
//                   packed xyz copy per CTA, redux argmax, tagged DSMEM
//                   mailboxes + all-thread dependent polls), 512 threads /
//                   4 packed slots, loop-invariant coords hoisted; publishes
//                   progress via st.release.gpu after each centroid write.
//  blocks 16..151 : workers. warp 0 polls g_progress (acquire + nanosleep,
//                   136 pollers chip-wide) into volatile smem; warps 1..15
//                   each consume centroids (ball query + MLP + max-pool) as
//                   they are produced. Centroid coords read via __ldcg (L2)
//                   to avoid stale L1 lines.
// FPS never waits on workers; workers wait only on monotonic progress.
// ---------------------------------------------------------------------------
__global__ __launch_bounds__(512, 1) __cluster_dims__(CL, 1, 1)
void fused_kernel(const float* __restrict__ xyz, const float* __restrict__ feat,
                  const float* __restrict__ w1, const float* __restrict__ b1,
                  const float* __restrict__ w2, const float* __restrict__ b2,
                  const float* __restrict__ w3, const float* __restrict__ b3,
                  float* __restrict__ newxyz, float* __restrict__ outf) {
    extern __shared__ unsigned char smraw[];
    __shared__ u64 s_part[32];
    __shared__ u64 mbox[2][CL];
    __shared__ volatile int s_prog[BB];
    __shared__ int s_idx[16][NS];

    const int tid = threadIdx.x;
    const int lane = tid & 31, wid = tid >> 5;

    if (blockIdx.x < NFPS) {
        // =================== FPS path ===================
        ulonglong2* A = (ulonglong2*)smraw;          // 8192 x 16B = 128 KB
        u64* Z = (u64*)(smraw + 8192 * 16);          // 8192 x 8B  =  64 KB
        const int b = blockIdx.x / CL;
        const int rank = blockIdx.x % CL;
        const float* base = xyz + (size_t)b * NN * 3;

        // full packed copy (every CTA); slot s packs points (s, s+8192)
        for (int s = tid; s < 8192; s += 512) {
            const int ia = s, ib = s + 8192;
            ulonglong2 av;
            av.x = f2_pack(base[3 * ia + 0], base[3 * ib + 0]);
            av.y = f2_pack(base[3 * ia + 1], base[3 * ib + 1]);
            A[s] = av;
            Z[s] = f2_pack(base[3 * ia + 2], base[3 * ib + 2]);
        }
        if (tid < 2 * CL) ((u64*)mbox)[tid] = 0;  // tags start at 1
        if (tid < 32) s_part[tid] = 0;            // lanes 16..31 stay 0 (never win)

        // this thread's 4 packed slots
        int sl[4];
        uint32_t nia[4], nib[4];
#pragma unroll
        for (int k = 0; k < 4; k++) {
            sl[k] = rank * 2048 + tid + k * 512;
            nia[k] = (uint32_t)(16383 - sl[k]);
            nib[k] = (uint32_t)(16383 - (sl[k] + 8192));
        }
        float2 dd[4];
#pragma unroll
        for (int k = 0; k < 4; k++) dd[k] = make_float2(1e10f, 1e10f);

        __syncthreads();
        cluster_sync_all();  // tiles + mailboxes initialized cluster-wide

        // hoist loop-invariant point coords into registers
        ulonglong2 av[4];
        u64 zv[4];
#pragma unroll
        for (int k = 0; k < 4; k++) {
            av[k] = A[sl[k]];
            zv[k] = Z[sl[k]];
        }

        int f = 0;
        float* outp = newxyz + (size_t)b * NPT * 3;
        const uint32_t mb0 = smem_u32(&mbox[0][0]);

        for (int p = 0; p < NPT; ++p) {
            const int fslot = f & 8191;
            const int fhalf = f >> 13;
            const ulonglong2 fa = A[fslot];
            const float2 fx = f2_unpack(fa.x);
            const float2 fy = f2_unpack(fa.y);
            const float2 fz = f2_unpack(Z[fslot]);
            const float cx = fhalf ? fx.y : fx.x;
            const float cy = fhalf ? fy.y : fy.x;
            const float cz = fhalf ? fz.y : fz.x;
            if (rank == 0 && tid == 0) {
                outp[3 * p + 0] = cx;
                outp[3 * p + 1] = cy;
                outp[3 * p + 2] = cz;
                st_release_gpu(&g_progress[b], p + 1);  // centroids 0..p ready
            }
            if (p == NPT - 1) break;  // last centroid published; skip dead work

            const u64 ncx = f2_pack(-cx, -cx);
            const u64 ncy = f2_pack(-cy, -cy);
            const u64 ncz = f2_pack(-cz, -cz);

            u64 loc = 0;
#pragma unroll
            for (int k = 0; k < 4; k++) {
                const u64 dx = f2_add(av[k].x, ncx);
                const u64 dy = f2_add(av[k].y, ncy);
                const u64 dz = f2_add(zv[k], ncz);
                const float2 d = f2_unpack(
                    f2_add(f2_add(f2_mul(dx, dx), f2_mul(dy, dy)), f2_mul(dz, dz)));
                dd[k].x = fminf(dd[k].x, d.x);
                dd[k].y = fminf(dd[k].y, d.y);
                const u64 k0 = ((u64)__float_as_uint(dd[k].x) << 21) | nia[k];
                const u64 k1 = ((u64)__float_as_uint(dd[k].y) << 21) | nib[k];
                loc = umax64(loc, umax64(k0, k1));
            }

            // warp argmax via two redux ops
            {
                const uint32_t dbits = (uint32_t)(loc >> 21);
                const uint32_t wmax = redux_max(dbits);
                const uint32_t cand = (dbits == wmax) ? (uint32_t)(loc & 0x3FFFu) : 0u;
                const uint32_t nmax = redux_max(cand);
                if (lane == 0) s_part[wid] = ((u64)wmax << 21) | nmax;
            }
            __syncthreads();

            const int par = p & 1;
            const u64 tag = (u64)(p + 1);
            if (wid == 0) {
                const u64 v = s_part[lane];
                const uint32_t dbits = (uint32_t)(v >> 21);
                const uint32_t wmax = redux_max(dbits);
                const uint32_t cand = (dbits == wmax) ? (uint32_t)(v & 0x3FFFu) : 0u;
                const uint32_t nmax = redux_max(cand);
                const u64 msg = (tag << 53) | ((u64)wmax << 21) | nmax;
                if (lane < CL)
                    st_cluster_u64(mb0 + (uint32_t)(par * CL + rank) * 8u, (uint32_t)lane,
                                   msg);
            }

            // round-4 tail: all threads, 4 dependent polls
            const uint32_t a0 = mb0 + (uint32_t)(par * CL) * 8u;
            u64 g = 0;
#pragma unroll
            for (int j = 0; j < CL; j++) {
                u64 v;
                do {
                    v = ld_mbox(a0 + (uint32_t)j * 8u);
                } while ((v >> 53) != tag);
                g = umax64(g, v);
            }
            f = 16383 - (int)(g & 0x3FFFu);
        }
        cluster_sync_all();  // no CTA exits while peers may still store into it
        return;
    }

    // =================== worker path ===================
    float* smf = (float*)smraw;
    float* sw1 = smf;                // 64 x 68 (padded)
    float* sw2 = sw1 + 64 * 68;      // 64 x 64
    float* sw3 = sw2 + 64 * 64;      // 128 x 64
    float* sb1 = sw3 + 128 * 64;     // 64
    float* sb2 = sb1 + 64;           // 64
    float* sb3 = sb2 + 64;           // 128

    for (int i = tid; i < 64 * CIN; i += 512) sw1[(i / CIN) * 68 + (i % CIN)] = w1[i];
    for (int i = tid; i < 64 * 64; i += 512) sw2[i] = w2[i];
    for (int i = tid; i < 128 * 64; i += 512) sw3[i] = w3[i];
    if (tid < 64) {
        sb1[tid] = b1[tid];
        sb2[tid] = b2[tid];
    }
    if (tid < 128) sb3[tid] = b3[tid];
    if (tid < BB) s_prog[tid] = 0;
    __syncthreads();

    if (wid == 0) {
        // poller: mirror g_progress into smem until all batches complete
        if (lane < BB) {
            for (;;) {
                const int v = ld_acquire_gpu(&g_progress[lane]);
                s_prog[lane] = v;
                if (v >= NPT) break;
                __nanosleep(512);
            }
        }
        return;
    }

    const int widx = (blockIdx.x - NFPS) * WWARPS + (wid - 1);  // 0..2039

    for (int pc = widx; pc < BB * NPT; pc += TOTWW) {
        const int b = pc >> 10, p = pc & 1023;
        while (s_prog[b] <= p) __nanosleep(256);

        // centroid coords via L2 (avoid stale L1 lines)
        const float ccx = __ldcg(newxyz + (size_t)pc * 3 + 0);
        const float ccy = __ldcg(newxyz + (size_t)pc * 3 + 1);
        const float ccz = __ldcg(newxyz + (size_t)pc * 3 + 2);
        const float* px = xyz + (size_t)b * NN * 3;

        // ---- ball query (verified logic) ----
        {
            int count = 0;
            int first = 0;
            bool havefirst = false;
            for (int bs = 0; bs < NN; bs += 32) {
                const int i = bs + lane;
                const float dx = __fadd_rn(px[3 * i + 0], -ccx);
                const float dy = __fadd_rn(px[3 * i + 1], -ccy);
                const float dz = __fadd_rn(px[3 * i + 2], -ccz);
                const float d2 = __fadd_rn(
                    __fadd_rn(__fmul_rn(dx, dx), __fmul_rn(dy, dy)), __fmul_rn(dz, dz));
                const bool win = d2 < 0.01f;
                const unsigned m = __ballot_sync(0xffffffffu, win);
                if (m) {
                    if (!havefirst) {
                        first = bs + __ffs(m) - 1;
                        havefirst = true;
                    }
                    const int slot = count + __popc(m & ((1u << lane) - 1u));
                    if (win && slot < NS) s_idx[wid][slot] = i;
                    count += __popc(m);
                    if (count >= NS) break;
                }
            }
            if (lane >= count) s_idx[wid][lane] = first;
            __syncwarp();
        }

        // ---- gather + MLP + max-pool (verified logic) ----
        const int idx = s_idx[wid][lane];
        const float* P = xyz + ((size_t)b * NN + idx) * 3;

        float in[CIN];
        in[0] = P[0] - ccx;
        in[1] = P[1] - ccy;
        in[2] = P[2] - ccz;
        const float4* F = (const float4*)(feat + ((size_t)b * NN + idx) * CF);
#pragma unroll
        for (int q = 0; q < 16; q++) {
            const float4 v = F[q];
            in[3 + 4 * q] = v.x;
            in[4 + 4 * q] = v.y;
            in[5 + 4 * q] = v.z;
            in[6 + 4 * q] = v.w;
        }

        float h1[64] __attribute__((aligned(16)));
#pragma unroll 1
        for (int o = 0; o < 64; o += 8) {
            float acc[8];
#pragma unroll
            for (int j = 0; j < 8; j++) acc[j] = sb1[o + j];
#pragma unroll
            for (int c = 0; c < 64; c += 4) {
#pragma unroll
                for (int j = 0; j < 8; j++) {
                    const float4 w = *(const float4*)&sw1[(o + j) * 68 + c];
                    acc[j] = fmaf(in[c + 0], w.x, acc[j]);
                    acc[j] = fmaf(in[c + 1], w.y, acc[j]);
                    acc[j] = fmaf(in[c + 2], w.z, acc[j]);
                    acc[j] = fmaf(in[c + 3], w.w, acc[j]);
                }
            }
#pragma unroll
            for (int j = 0; j < 8; j++) {
                acc[j] = fmaf(in[64], sw1[(o + j) * 68 + 64], acc[j]);
                acc[j] = fmaf(in[65], sw1[(o + j) * 68 + 65], acc[j]);
                acc[j] = fmaf(in[66], sw1[(o + j) * 68 + 66], acc[j]);
                h1[o + j] = fmaxf(acc[j], 0.0f);
            }
        }

        float h2[64] __attribute__((aligned(16)));
#pragma unroll 1
        for (int o = 0; o < 64; o += 8) {
            float acc[8];
#pragma unroll
            for (int j = 0; j < 8; j++) acc[j] = sb2[o + j];
#pragma unroll
            for (int c = 0; c < 64; c += 4) {
                const float4 hv = *(const float4*)&h1[c];
#pragma unroll
                for (int j = 0; j < 8; j++) {
                    const float4 w = *(const float4*)&sw2[(o + j) * 64 + c];
                    acc[j] = fmaf(hv.x, w.x, acc[j]);
                    acc[j] = fmaf(hv.y, w.y, acc[j]);
                    acc[j] = fmaf(hv.z, w.z, acc[j]);
                    acc[j] = fmaf(hv.w, w.w, acc[j]);
                }
            }
#pragma unroll
            for (int j = 0; j < 8; j++) h2[o + j] = fmaxf(acc[j], 0.0f);
        }

        const size_t obase = ((size_t)b * 128) * NPT + p;
#pragma unroll 1
        for (int o = 0; o < 128; o += 8) {
            float acc[8];
#pragma unroll
            for (int j = 0; j < 8; j++) acc[j] = sb3[o + j];
#pragma unroll
            for (int c = 0; c < 64; c += 4) {
                const float4 hv = *(const float4*)&h2[c];
#pragma unroll
                for (int j = 0; j < 8; j++) {
                    const float4 w = *(const float4*)&sw3[(o + j) * 64 + c];
                    acc[j] = fmaf(hv.x, w.x, acc[j]);
                    acc[j] = fmaf(hv.y, w.y, acc[j]);
                    acc[j] = fmaf(hv.z, w.z, acc[j]);
                    acc[j] = fmaf(hv.w, w.w, acc[j]);
                }
            }
#pragma unroll
            for (int j = 0; j < 8; j++) {
                float v = fmaxf(acc[j], 0.0f);  // relu then max over samples
#pragma unroll
                for (int off = 16; off; off >>= 1)
                    v = fmaxf(v, __shfl_xor_sync(0xffffffffu, v, off));
                if (lane == 0) outf[obase + (size_t)(o + j) * NPT] = v;
            }
        }
    }
}

// ---------------------------------------------------------------------------
extern "C" void kernel_launch(void* const* d_in, const int* in_sizes, int n_in,
                              void* d_out, int out_size) {
    const float* xyz = (const float*)d_in[0];
    const float* feat = (const float*)d_in[1];
    const float* w1 = (const float*)d_in[2];
    const float* b1 = (const float*)d_in[3];
    const float* w2 = (const float*)d_in[4];
    const float* b2 = (const float*)d_in[5];
    const float* w3 = (const float*)d_in[6];
    const float* b3 = (const float*)d_in[7];

    float* out = (float*)d_out;
    float* newxyz = out;               // (B, NPOINT, 3)
    float* outf = out + BB * NPT * 3;  // (B, 128, NPOINT)

    const int smem = 8192 * 16 + 8192 * 8;  // 196608 B (FPS packed copy; workers use less)

    cudaFuncSetAttribute(fused_kernel, cudaFuncAttributeMaxDynamicSharedMemorySize, smem);

    reset_kernel<<<1, 32>>>();
    fused_kernel<<<NFPS + NWORK, 512, smem>>>(xyz, feat, w1, b1, w2, b2, w3, b3, newxyz,
                                              outf);
}